// round 16
// baseline (speedup 1.0000x reference)
#include <cuda_runtime.h>
#include <math.h>
#include <stdint.h>

#define NG 50000
#define ND 25000
#define CH 128
#define HC 512   // H*C = 4*128

typedef unsigned long long ull;

// ---------------- scratch (device globals: no allocation allowed) ----------
__device__ float g_hg[(size_t)NG * CH];     // encoded gene (pre-BN)
__device__ float g_hd[(size_t)ND * CH];     // encoded dis  (pre-BN)
__device__ float g_gene1[(size_t)NG * CH];  // gene after GAT1
__device__ float g_agg[(size_t)NG * CH];    // GAT aggregation buffer
__device__ float g_xs[(size_t)NG * HC];     // xs = x_src @ Ws (reused both GATs)
__device__ float g_ls[NG * 4];
__device__ float g_ld[NG * 4];
__device__ float g_m[NG * 4];
__device__ float g_den[NG * 4];
__device__ float g_wld[CH * 4];             // (scaled) Wd @ a_d, layout [k][h]
__device__ float g_wldraw[CH * 4];          // unscaled Wd @ a_d
__device__ float g_wldc[4];                 // shift term for ld
__device__ float g_stats[4 * CH];           // sumG, sqG, sumD, sqD
__device__ float g_bnp[4 * CH];             // scaleG, shiftG, scaleD, shiftD
__device__ float g_w1sf[CH * HC];           // diag(scD) @ W1s
__device__ float g_shW[HC];                 // shD @ W1s

// ---------------- helpers --------------------------------------------------
__device__ __forceinline__ void atomicMaxF(float* addr, float v) {
    if (v >= 0.0f) atomicMax((int*)addr, __float_as_int(v));
    else           atomicMin((unsigned int*)addr, __float_as_uint(v));
}

__device__ __forceinline__ float lrelu02(float x) {
    return x > 0.0f ? x : 0.2f * x;
}

__device__ __forceinline__ ull pk2(float x, float y) {
    ull r;
    asm("mov.b64 %0, {%1, %2};" : "=l"(r) : "f"(x), "f"(y));
    return r;
}

#define FMA2(c, a, b) \
    asm("fma.rn.f32x2 %0, %1, %2, %0;" : "+l"(c) : "l"(a), "l"(b))

// ---------------- generic fill ---------------------------------------------
__global__ void fill_kernel(float* __restrict__ p, float v, int n) {
    int i = blockIdx.x * blockDim.x + threadIdx.x;
    if (i < n) p[i] = v;
}

// one launch inits agg (0), m (-inf), den (0) for a GAT layer
__global__ void gat_init_kernel(float* __restrict__ agg, float* __restrict__ m,
                                float* __restrict__ den, int nAgg, int nHeads)
{
    int i = blockIdx.x * blockDim.x + threadIdx.x;
    if (i < nAgg) agg[i] = 0.f;
    if (i < nHeads) { m[i] = -INFINITY; den[i] = 0.f; }
}

// ---------------- SGEMM (zero-mov FFMA2): C = A @ B (+bias/relu) -----------
// BM=BN=128, BK=16. 128 threads, 16x8 microtile (8 row-pairs x 8 cols).
// A operands: row-pair ulls direct from As (LDS.128).
// B operands: pre-duplicated {b,b} pairs in permuted Bs (conflict-free LDS.128).
// mode: 0 = none, 1 = bias+relu, 2 = bias only
__global__ __launch_bounds__(128, 2)
void sgemm_kernel(const float* __restrict__ A, const float* __restrict__ B,
                  const float* __restrict__ bias, float* __restrict__ C,
                  int M, int N, int K, int mode)
{
    __shared__ float As[16][128];   // As[k][m]
    __shared__ ull   Bs[16][128];   // dup pairs, permuted: pair p at unit (p&3)*16+(p>>2)

    const int tid = threadIdx.x;
    const int tx = tid & 15;        // 16 col groups x 8 cols
    const int ty = tid >> 4;        // 8 row groups x 16 rows
    const int row0 = blockIdx.y * 128;
    const int col0 = blockIdx.x * 128;

    ull acc[8][8];                  // [row-pair i2][col j]
#pragma unroll
    for (int i2 = 0; i2 < 8; i2++)
#pragma unroll
        for (int j = 0; j < 8; j++) acc[i2][j] = 0ull;

    for (int k0 = 0; k0 < K; k0 += 16) {
        // ---- A tile: thread 'tid' owns global row row0+tid (16 k-values) ----
        {
            int gr = row0 + tid;
            float4 v0, v1, v2, v3;
            if (gr < M) {
                const float4* ap = (const float4*)&A[(size_t)gr * K + k0];
                v0 = ap[0]; v1 = ap[1]; v2 = ap[2]; v3 = ap[3];
            } else {
                v0 = v1 = v2 = v3 = make_float4(0.f, 0.f, 0.f, 0.f);
            }
            As[0][tid] = v0.x;  As[1][tid] = v0.y;  As[2][tid] = v0.z;  As[3][tid] = v0.w;
            As[4][tid] = v1.x;  As[5][tid] = v1.y;  As[6][tid] = v1.z;  As[7][tid] = v1.w;
            As[8][tid] = v2.x;  As[9][tid] = v2.y;  As[10][tid] = v2.z; As[11][tid] = v2.w;
            As[12][tid] = v3.x; As[13][tid] = v3.y; As[14][tid] = v3.z; As[15][tid] = v3.w;
        }
        // ---- B tile: thread (k = tid>>3, t = tid&7) owns cols t*16..t*16+15 of row k ----
        {
            int k = tid >> 3, t = tid & 7;
            const float4* bp = (const float4*)&B[(size_t)(k0 + k) * N + col0 + t * 16];
#pragma unroll
            for (int q = 0; q < 4; q++) {
                float4 v = bp[q];
                float c4[4] = {v.x, v.y, v.z, v.w};
#pragma unroll
                for (int e = 0; e < 4; e++) {
                    int n = t * 16 + q * 4 + e;
                    int p = n >> 1;
                    int pos = (p & 3) * 16 + (p >> 2);   // 16B-unit index
                    Bs[k][pos * 2 + (n & 1)] = pk2(c4[e], c4[e]);
                }
            }
        }
        __syncthreads();

#pragma unroll
        for (int k = 0; k < 16; k++) {
            ull a2[8], b2[8];
            const ulonglong2* ap = (const ulonglong2*)&As[k][ty * 16];
#pragma unroll
            for (int i4 = 0; i4 < 4; i4++) {
                ulonglong2 t = ap[i4];
                a2[i4 * 2] = t.x; a2[i4 * 2 + 1] = t.y;
            }
            const ulonglong2* bp = (const ulonglong2*)&Bs[k][0];
#pragma unroll
            for (int j4 = 0; j4 < 4; j4++) {
                ulonglong2 t = bp[j4 * 16 + tx];   // pair p = tx*4 + j4 -> cols tx*8+j4*2{,+1}
                b2[j4 * 2] = t.x; b2[j4 * 2 + 1] = t.y;
            }
#pragma unroll
            for (int i2 = 0; i2 < 8; i2++)
#pragma unroll
                for (int j = 0; j < 8; j++)
                    FMA2(acc[i2][j], a2[i2], b2[j]);
        }
        __syncthreads();
    }

    // ---- epilogue ----
    // col j of thread = col0 + tx*8 + (j4*2+e) where b2 index j = j4*2+e
#pragma unroll
    for (int i2 = 0; i2 < 8; i2++) {
#pragma unroll
        for (int sel = 0; sel < 2; sel++) {
            int gr = row0 + ty * 16 + i2 * 2 + sel;
            if (gr >= M) continue;
            float vals[8];
#pragma unroll
            for (int j = 0; j < 8; j++) {
                float lo, hi;
                asm("mov.b64 {%0, %1}, %2;" : "=f"(lo), "=f"(hi) : "l"(acc[i2][j]));
                vals[j] = sel ? hi : lo;
            }
            int gc = col0 + tx * 8;
            if (mode == 1) {
#pragma unroll
                for (int j = 0; j < 8; j++) vals[j] = fmaxf(vals[j] + bias[gc + j], 0.f);
            } else if (mode == 2) {
#pragma unroll
                for (int j = 0; j < 8; j++) vals[j] = vals[j] + bias[gc + j];
            }
            float4 v0 = make_float4(vals[0], vals[1], vals[2], vals[3]);
            float4 v1 = make_float4(vals[4], vals[5], vals[6], vals[7]);
            *(float4*)&C[(size_t)gr * N + gc]     = v0;
            *(float4*)&C[(size_t)gr * N + gc + 4] = v1;
        }
    }
}

// ---------------- BN: column stats (sum, sumsq) ----------------------------
__global__ void colstats_kernel(const float* __restrict__ X, int rows,
                                float* __restrict__ sum, float* __restrict__ sq)
{
    int c = threadIdx.x;               // 128 threads
    int r0 = blockIdx.x * 128;
    int r1 = min(r0 + 128, rows);
    float s = 0.f, q = 0.f;
    for (int r = r0; r < r1; r++) {
        float v = X[(size_t)r * CH + c];
        s += v;
        q += v * v;
    }
    atomicAdd(&sum[c], s);
    atomicAdd(&sq[c], q);
}

__global__ void bn_finalize_kernel(const float* __restrict__ gg, const float* __restrict__ betag,
                                   const float* __restrict__ gd, const float* __restrict__ betad)
{
    int t = threadIdx.x;  // 256
    if (t < 128) {
        float mu  = g_stats[t] / (float)NG;
        float var = fmaxf(g_stats[128 + t] / (float)NG - mu * mu, 0.f);
        float sc  = gg[t] * rsqrtf(var + 1e-5f);
        g_bnp[t]       = sc;
        g_bnp[128 + t] = betag[t] - mu * sc;
    } else {
        int c = t - 128;
        float mu  = g_stats[256 + c] / (float)ND;
        float var = fmaxf(g_stats[384 + c] / (float)ND - mu * mu, 0.f);
        float sc  = gd[c] * rsqrtf(var + 1e-5f);
        g_bnp[256 + c] = sc;
        g_bnp[384 + c] = betad[c] - mu * sc;
    }
}

// ---------------- fold BN into W1s: W' = diag(sc)W, shW = sh @ W ------------
__global__ void scaleW_kernel(const float* __restrict__ W) {
    int j = blockIdx.x * blockDim.x + threadIdx.x;
    if (j >= HC) return;
    const float* sc = g_bnp + 256;   // disease scale
    const float* sh = g_bnp + 384;   // disease shift
    float acc = 0.f;
#pragma unroll 4
    for (int k = 0; k < CH; k++) {
        float w = W[(size_t)k * HC + j];
        g_w1sf[(size_t)k * HC + j] = w * sc[k];
        acc += sh[k] * w;
    }
    g_shW[j] = acc;
}

// ---------------- ls[n,h] = sum_c xs[n, h*128+c] * a_s[h,c] ----------------
__global__ void ls_kernel(const float* __restrict__ a_s, int n) {
    int w = (blockIdx.x * blockDim.x + threadIdx.x) >> 5;
    int lane = threadIdx.x & 31;
    if (w >= n) return;
    const float4* xr = (const float4*)(g_xs + (size_t)w * HC);
    const float4* ar = (const float4*)a_s;
    float p0, p1, p2, p3;
    {
        float4 x = xr[lane],      a = ar[lane];
        p0 = x.x * a.x + x.y * a.y + x.z * a.z + x.w * a.w;
    }
    {
        float4 x = xr[32 + lane], a = ar[32 + lane];
        p1 = x.x * a.x + x.y * a.y + x.z * a.z + x.w * a.w;
    }
    {
        float4 x = xr[64 + lane], a = ar[64 + lane];
        p2 = x.x * a.x + x.y * a.y + x.z * a.z + x.w * a.w;
    }
    {
        float4 x = xr[96 + lane], a = ar[96 + lane];
        p3 = x.x * a.x + x.y * a.y + x.z * a.z + x.w * a.w;
    }
#pragma unroll
    for (int off = 16; off > 0; off >>= 1) {
        p0 += __shfl_xor_sync(0xffffffffu, p0, off);
        p1 += __shfl_xor_sync(0xffffffffu, p1, off);
        p2 += __shfl_xor_sync(0xffffffffu, p2, off);
        p3 += __shfl_xor_sync(0xffffffffu, p3, off);
    }
    if (lane == 0) *(float4*)&g_ls[w * 4] = make_float4(p0, p1, p2, p3);
}

// ---------------- wld[k,h] = sum_c Wd[k, h*128+c] * a_d[h,c] ---------------
__global__ void wld_kernel(const float* __restrict__ Wd, const float* __restrict__ a_d,
                           int useScale) {
    int w = (blockIdx.x * blockDim.x + threadIdx.x) >> 5;
    int lane = threadIdx.x & 31;
    if (w >= 512) return;
    int k = w >> 2, h = w & 3;
    const float4* wr = (const float4*)(Wd + (size_t)k * HC + h * 128);
    const float4* ar = (const float4*)(a_d + h * 128);
    float4 x = wr[lane], a = ar[lane];
    float p = x.x * a.x + x.y * a.y + x.z * a.z + x.w * a.w;
#pragma unroll
    for (int off = 16; off > 0; off >>= 1) p += __shfl_xor_sync(0xffffffffu, p, off);
    if (lane == 0) {
        g_wldraw[k * 4 + h] = p;
        g_wld[k * 4 + h] = useScale ? p * g_bnp[k] : p;
    }
}

// c[h] = sum_k shG[k] * wldraw[k,h]  (one block, 128 threads)
__global__ void ldc_kernel() {
    int k = threadIdx.x;
    if (k < 4) g_wldc[k] = 0.f;
    __syncthreads();
    float sh = g_bnp[128 + k];
#pragma unroll
    for (int h = 0; h < 4; h++)
        atomicAdd(&g_wldc[h], sh * g_wldraw[k * 4 + h]);
}

// ---------------- ld[n,h] = sum_k X[n,k] * wld[k,h] + c[h] -----------------
__global__ void ld_kernel(const float* __restrict__ X, int n) {
    int w = (blockIdx.x * blockDim.x + threadIdx.x) >> 5;
    int lane = threadIdx.x & 31;
    if (w >= n) return;
    const float4* xr = (const float4*)(X + (size_t)w * CH);
    float4 x = xr[lane];
    const float4* wl = (const float4*)g_wld;   // wl[k] = 4 heads of k
    float4 p = make_float4(0.f, 0.f, 0.f, 0.f);
    float4 wv;
    wv = wl[lane * 4 + 0]; p.x += x.x * wv.x; p.y += x.x * wv.y; p.z += x.x * wv.z; p.w += x.x * wv.w;
    wv = wl[lane * 4 + 1]; p.x += x.y * wv.x; p.y += x.y * wv.y; p.z += x.y * wv.z; p.w += x.y * wv.w;
    wv = wl[lane * 4 + 2]; p.x += x.z * wv.x; p.y += x.z * wv.y; p.z += x.z * wv.z; p.w += x.z * wv.w;
    wv = wl[lane * 4 + 3]; p.x += x.w * wv.x; p.y += x.w * wv.y; p.z += x.w * wv.z; p.w += x.w * wv.w;
#pragma unroll
    for (int off = 16; off > 0; off >>= 1) {
        p.x += __shfl_xor_sync(0xffffffffu, p.x, off);
        p.y += __shfl_xor_sync(0xffffffffu, p.y, off);
        p.z += __shfl_xor_sync(0xffffffffu, p.z, off);
        p.w += __shfl_xor_sync(0xffffffffu, p.w, off);
    }
    if (lane == 0) {
        float4 c = *(const float4*)g_wldc;
        *(float4*)&g_ld[w * 4] = make_float4(p.x + c.x, p.y + c.y, p.z + c.z, p.w + c.w);
    }
}

// ---------------- edge pass A: segment max ---------------------------------
__global__ void edge_max_kernel(const int* __restrict__ src, const int* __restrict__ dst,
                                int nE, int nLoop)
{
    int e = blockIdx.x * blockDim.x + threadIdx.x;
    if (e >= nE + nLoop) return;
    int s, d;
    if (e < nE) { s = src[e]; d = dst[e]; if (s == d) return; }
    else        { s = d = e - nE; }
    float4 lsv = *(const float4*)&g_ls[s * 4];
    float4 ldv = *(const float4*)&g_ld[d * 4];
    atomicMaxF(&g_m[d * 4 + 0], lrelu02(lsv.x + ldv.x));
    atomicMaxF(&g_m[d * 4 + 1], lrelu02(lsv.y + ldv.y));
    atomicMaxF(&g_m[d * 4 + 2], lrelu02(lsv.z + ldv.z));
    atomicMaxF(&g_m[d * 4 + 3], lrelu02(lsv.w + ldv.w));
}

// ---------------- edge pass B: denominator ---------------------------------
__global__ void edge_den_kernel(const int* __restrict__ src, const int* __restrict__ dst,
                                int nE, int nLoop)
{
    int e = blockIdx.x * blockDim.x + threadIdx.x;
    if (e >= nE + nLoop) return;
    int s, d;
    if (e < nE) { s = src[e]; d = dst[e]; if (s == d) return; }
    else        { s = d = e - nE; }
    float4 lsv = *(const float4*)&g_ls[s * 4];
    float4 ldv = *(const float4*)&g_ld[d * 4];
    float4 mv  = *(const float4*)&g_m[d * 4];
    atomicAdd(&g_den[d * 4 + 0], expf(lrelu02(lsv.x + ldv.x) - mv.x));
    atomicAdd(&g_den[d * 4 + 1], expf(lrelu02(lsv.y + ldv.y) - mv.y));
    atomicAdd(&g_den[d * 4 + 2], expf(lrelu02(lsv.z + ldv.z) - mv.z));
    atomicAdd(&g_den[d * 4 + 3], expf(lrelu02(lsv.w + ldv.w) - mv.w));
}

// ---------------- edge pass C: weighted aggregation (warp per edge) --------
__global__ void edge_agg_kernel(const int* __restrict__ src, const int* __restrict__ dst,
                                int nE, int nLoop)
{
    int gw = (blockIdx.x * blockDim.x + threadIdx.x) >> 5;
    int lane = threadIdx.x & 31;
    if (gw >= nE + nLoop) return;
    int s, d;
    if (gw < nE) { s = src[gw]; d = dst[gw]; if (s == d) return; }
    else         { s = d = gw - nE; }
    float4 lsv = *(const float4*)&g_ls[s * 4];
    float4 ldv = *(const float4*)&g_ld[d * 4];
    float4 mv  = *(const float4*)&g_m[d * 4];
    float4 dv  = *(const float4*)&g_den[d * 4];
    float l;
    l = lsv.x + ldv.x; l = lrelu02(l);
    float a0 = 0.25f * expf(l - mv.x) / (dv.x > 0.f ? dv.x : 1.f);
    l = lsv.y + ldv.y; l = lrelu02(l);
    float a1 = 0.25f * expf(l - mv.y) / (dv.y > 0.f ? dv.y : 1.f);
    l = lsv.z + ldv.z; l = lrelu02(l);
    float a2 = 0.25f * expf(l - mv.z) / (dv.z > 0.f ? dv.z : 1.f);
    l = lsv.w + ldv.w; l = lrelu02(l);
    float a3 = 0.25f * expf(l - mv.w) / (dv.w > 0.f ? dv.w : 1.f);

    const float4* xr = (const float4*)(g_xs + (size_t)s * HC);
    float4 v, acc;
    v = xr[lane];
    acc.x = a0 * v.x; acc.y = a0 * v.y; acc.z = a0 * v.z; acc.w = a0 * v.w;
    v = xr[32 + lane];
    acc.x += a1 * v.x; acc.y += a1 * v.y; acc.z += a1 * v.z; acc.w += a1 * v.w;
    v = xr[64 + lane];
    acc.x += a2 * v.x; acc.y += a2 * v.y; acc.z += a2 * v.z; acc.w += a2 * v.w;
    v = xr[96 + lane];
    acc.x += a3 * v.x; acc.y += a3 * v.y; acc.z += a3 * v.z; acc.w += a3 * v.w;

    float* p = &g_agg[(size_t)d * CH + lane * 4];
    asm volatile("red.global.add.v4.f32 [%0], {%1,%2,%3,%4};"
                 :: "l"(p), "f"(acc.x), "f"(acc.y), "f"(acc.z), "f"(acc.w)
                 : "memory");
}

// ---------------- combine variants -----------------------------------------
__global__ void combine_affine_kernel(const float* __restrict__ base,
                                      const float* __restrict__ bias,
                                      float* __restrict__ out, int n)
{
    int i = blockIdx.x * blockDim.x + threadIdx.x;
    if (i < n) {
        int c = i & 127;
        out[i] = base[i] * g_bnp[c] + g_bnp[128 + c] + g_agg[i] + bias[c];
    }
}

__global__ void combine_kernel(const float* __restrict__ base, const float* __restrict__ bias,
                               float* __restrict__ out, int n)
{
    int i = blockIdx.x * blockDim.x + threadIdx.x;
    if (i < n) {
        int c = i & 127;
        out[i] = base[i] + g_agg[i] + bias[c];
    }
}

__global__ void copy_affine_kernel(const float* __restrict__ srcp,
                                   float* __restrict__ dstp, int n) {
    int i = blockIdx.x * blockDim.x + threadIdx.x;
    if (i < n) {
        int c = i & 127;
        dstp[i] = srcp[i] * g_bnp[256 + c] + g_bnp[384 + c];
    }
}

// ---------------- host orchestration ---------------------------------------
extern "C" void kernel_launch(void* const* d_in, const int* in_sizes, int n_in,
                              void* d_out, int out_size)
{
    const float* x_gene = (const float*)d_in[0];
    const float* x_dis  = (const float*)d_in[1];
    const int* e1_src   = (const int*)d_in[2];
    const int* e1_dst   = (const int*)d_in[3];
    const int* e2_src   = (const int*)d_in[4];
    const int* e2_dst   = (const int*)d_in[5];
    const float* Wg     = (const float*)d_in[6];
    const float* bg     = (const float*)d_in[7];
    const float* gg     = (const float*)d_in[8];
    const float* betag  = (const float*)d_in[9];
    const float* Wd     = (const float*)d_in[10];
    const float* bd     = (const float*)d_in[11];
    const float* gd     = (const float*)d_in[12];
    const float* betad  = (const float*)d_in[13];
    const float* W1s    = (const float*)d_in[14];
    const float* W1d    = (const float*)d_in[15];
    const float* a1s    = (const float*)d_in[16];
    const float* a1d    = (const float*)d_in[17];
    const float* b1     = (const float*)d_in[18];
    const float* W2s    = (const float*)d_in[19];
    const float* W2d    = (const float*)d_in[20];
    const float* a2s    = (const float*)d_in[21];
    const float* a2d    = (const float*)d_in[22];
    const float* b2     = (const float*)d_in[23];

    const int E1 = in_sizes[2];
    const int E2 = in_sizes[4];
    const int Fg = in_sizes[0] / NG;   // 512
    const int Fd = in_sizes[1] / ND;   // 256

    float *hg, *hd, *gene1, *xs, *agg, *mbuf, *den, *stats, *w1sf, *shW, *wldc;
    cudaGetSymbolAddress((void**)&hg, g_hg);
    cudaGetSymbolAddress((void**)&hd, g_hd);
    cudaGetSymbolAddress((void**)&gene1, g_gene1);
    cudaGetSymbolAddress((void**)&xs, g_xs);
    cudaGetSymbolAddress((void**)&agg, g_agg);
    cudaGetSymbolAddress((void**)&mbuf, g_m);
    cudaGetSymbolAddress((void**)&den, g_den);
    cudaGetSymbolAddress((void**)&stats, g_stats);
    cudaGetSymbolAddress((void**)&w1sf, g_w1sf);
    cudaGetSymbolAddress((void**)&shW, g_shW);
    cudaGetSymbolAddress((void**)&wldc, g_wldc);

    float* out_gene = (float*)d_out;
    float* out_dis  = (float*)d_out + (size_t)NG * CH;

    const int T = 256;
    auto blocks = [](int n, int t) { return (n + t - 1) / t; };

    // -------- encoders (pre-BN activations) --------
    fill_kernel<<<2, T>>>(stats, 0.f, 4 * CH);
    sgemm_kernel<<<dim3(1, blocks(NG, 128)), 128>>>(x_gene, Wg, bg, hg, NG, CH, Fg, 1);
    sgemm_kernel<<<dim3(1, blocks(ND, 128)), 128>>>(x_dis,  Wd, bd, hd, ND, CH, Fd, 1);
    colstats_kernel<<<blocks(NG, 128), 128>>>(hg, NG, stats, stats + 128);
    colstats_kernel<<<blocks(ND, 128), 128>>>(hd, ND, stats + 256, stats + 384);
    bn_finalize_kernel<<<1, 256>>>(gg, betag, gd, betad);
    scaleW_kernel<<<2, 256>>>(W1s);   // fold disease BN into W1s

    // -------- GAT 1: dis -> gene --------
    gat_init_kernel<<<blocks(NG * CH, T), T>>>(agg, mbuf, den, NG * CH, NG * 4);
    // xs = BN(hd) @ W1s = hd @ W1s' + shW
    sgemm_kernel<<<dim3(4, blocks(ND, 128)), 128>>>(hd, w1sf, shW, xs, ND, HC, CH, 2);
    ls_kernel<<<blocks(ND * 32, T), T>>>(a1s, ND);
    wld_kernel<<<blocks(512 * 32, T), T>>>(W1d, a1d, 1);  // scaled by gene BN
    ldc_kernel<<<1, 128>>>();
    ld_kernel<<<blocks(NG * 32, T), T>>>(hg, NG);         // ld = BN(hg)@wld folded
    {
        int nT = E1 + ND;
        edge_max_kernel<<<blocks(nT, T), T>>>(e1_src, e1_dst, E1, ND);
        edge_den_kernel<<<blocks(nT, T), T>>>(e1_src, e1_dst, E1, ND);
        edge_agg_kernel<<<blocks(nT * 32, T), T>>>(e1_src, e1_dst, E1, ND);
    }
    combine_affine_kernel<<<blocks(NG * CH, T), T>>>(hg, b1, gene1, NG * CH);

    // -------- GAT 2: gene -> gene --------
    gat_init_kernel<<<blocks(NG * CH, T), T>>>(agg, mbuf, den, NG * CH, NG * 4);
    sgemm_kernel<<<dim3(4, blocks(NG, 128)), 128>>>(gene1, W2s, nullptr, xs, NG, HC, CH, 0);
    ls_kernel<<<blocks(NG * 32, T), T>>>(a2s, NG);
    wld_kernel<<<blocks(512 * 32, T), T>>>(W2d, a2d, 0);  // no BN fold
    fill_kernel<<<1, 32>>>(wldc, 0.f, 4);
    ld_kernel<<<blocks(NG * 32, T), T>>>(gene1, NG);
    {
        int nT = E2 + NG;
        edge_max_kernel<<<blocks(nT, T), T>>>(e2_src, e2_dst, E2, NG);
        edge_den_kernel<<<blocks(nT, T), T>>>(e2_src, e2_dst, E2, NG);
        edge_agg_kernel<<<blocks(nT * 32, T), T>>>(e2_src, e2_dst, E2, NG);
    }

    // -------- outputs: [gene | dis] --------
    combine_kernel<<<blocks(NG * CH, T), T>>>(gene1, b2, out_gene, NG * CH);
    copy_affine_kernel<<<blocks(ND * CH, T), T>>>(hd, out_dis, ND * CH);
}